// round 16
// baseline (speedup 1.0000x reference)
#include <cuda_runtime.h>
#include <cuda_bf16.h>

typedef unsigned long long ull;

// Problem constants
#define BB    8
#define NN    4096
#define WROW  128          // 4096/32 bitmask words per row
#define ROWS  (BB*NN)      // 32768
#define INDIM 16420
#define HID   128
#define NACT  16
#define FCSPLIT 512        // fc1 split-K chunks (shared across batches)
#define CK    33           // fc1 chunk size (512*33 >= 16420)
#define NQ    16           // column strips per row in agg (256 cols each)

// Bit layout (permuted, consistent between prep and agg):
//   word (rd*4 + e), bit l  <->  column rd*128 + l*4 + e     (rd 0..31, e 0..3, l 0..31)

// ---------------- scratch (static __device__, no allocations) ----------------
__device__ unsigned g_bits[(size_t)ROWS * WROW];   // 16 MB packed adjacency (with self loops)
__device__ float    g_dinv[ROWS];
__device__ float4   g_v [ROWS];                    // dinv * (x @ W1)
__device__ float4   g_v2[ROWS];                    // dinv * (h @ W2)
__device__ float4   g_h2[ROWS];                    // final GCN output h (layer2)
__device__ float4   g_pa[NQ * ROWS];               // layer1 partial sums (col strips)
__device__ float4   g_pb[NQ * ROWS];               // layer2 partial sums
__device__ float    g_zacc[BB * HID];
__device__ unsigned g_ctr0[BB * 16];               // agg1 arrival counters per (b,rt)
__device__ unsigned g_ctr1[BB * 16];               // agg2 arrival counters
__device__ unsigned g_fcc;                         // fc1 arrival counter

// ---------------- K1: adj -> bitmask + dinv + v1 + zacc + counter reset --------
__global__ void __launch_bounds__(256) prep_kernel(
    const int* __restrict__ adj, const float* __restrict__ x,
    const float* __restrict__ W1, const float* __restrict__ fcb1)
{
    int t    = threadIdx.x;
    int warp = (blockIdx.x * 256 + t) >> 5;   // 0..32767 = row
    int lane = t & 31;
    int row  = warp;
    int i    = row & (NN - 1);

    // fused init (block 0): zacc biases + arrival counters
    if (blockIdx.x == 0) {
#pragma unroll
        for (int r = 0; r < 4; ++r) {
            int idx = r * 256 + t;
            g_zacc[idx] = fcb1[idx & (HID - 1)];
        }
        if (t < BB * 16) { g_ctr0[t] = 0u; g_ctr1[t] = 0u; }
        if (t == 0) g_fcc = 0u;
    }

    const int4* arow = (const int4*)(adj + ((size_t)row << 12));
    unsigned*   brow = g_bits + ((size_t)row << 7);
    uint4*      brow4 = (uint4*)brow;

    // self-loop target: word tw, bit tb (permuted layout)
    int tw = (i >> 7) * 4 + (i & 3);
    unsigned tb = 1u << ((i >> 2) & 31);

    int4 buf[8];
#pragma unroll
    for (int p = 0; p < 8; ++p)
        buf[p] = __ldcs(&arow[p * 32 + lane]);

    unsigned cnt = 0;   // warp-uniform

#pragma unroll 1
    for (int g = 0; g < 4; ++g) {
        int4 cur[8];
#pragma unroll
        for (int p = 0; p < 8; ++p) cur[p] = buf[p];
        if (g < 3) {
#pragma unroll
            for (int p = 0; p < 8; ++p)
                buf[p] = __ldcs(&arow[(g + 1) * 256 + p * 32 + lane]);
        }
#pragma unroll
        for (int p = 0; p < 8; ++p) {
            int rd = g * 8 + p;
            int4 v = cur[p];
            unsigned b0 = __ballot_sync(0xffffffffu, v.x != 0);
            unsigned b1 = __ballot_sync(0xffffffffu, v.y != 0);
            unsigned b2 = __ballot_sync(0xffffffffu, v.z != 0);
            unsigned b3 = __ballot_sync(0xffffffffu, v.w != 0);
            if (lane == 0)
                brow4[rd] = make_uint4(b0, b1, b2, b3);
            cnt += __popc(b0) + __popc(b1) + __popc(b2) + __popc(b3);
        }
    }

    // self-loop post-fix + dinv + v1 (lane 0; cnt is uniform)
    if (lane == 0) {
        unsigned wv = brow[tw];
        cnt += ((wv & tb) == 0u);
        brow[tw] = wv | tb;
        float d = rsqrtf((float)cnt);
        g_dinv[row] = d;
        float x0 = x[row*3], x1 = x[row*3+1], x2 = x[row*3+2];
        float u0 = x0*W1[0] + x1*W1[3] + x2*W1[6];
        float u1 = x0*W1[1] + x1*W1[4] + x2*W1[7];
        float u2 = x0*W1[2] + x1*W1[5] + x2*W1[8];
        g_v[row] = make_float4(d*u0, d*u1, d*u2, 0.f);
    }
}

// ---------------- quad-LUT aggregation core (permuted bit order) ----------------
__device__ __forceinline__ void agg_core(
    const float4* __restrict__ vin, float4* __restrict__ part,
    int b, int rt, int s, int t)
{
    __shared__ float2 sxy[64 * 16];   // 8 KB
    __shared__ float  szl[64 * 16];   // 4 KB

    // ---- build LUTs: thread t -> quad t>>2, entries (t&3)*4 .. +4 ----
    {
        int quad = t >> 2;              // 0..63 = j*8 + k
        int j = quad >> 3, k = quad & 7;
        int base = b * NN + s * 256 + (j >> 2) * 128 + k * 16 + (j & 3);
        float4 v0 = vin[base], v1 = vin[base + 4], v2 = vin[base + 8], v3 = vin[base + 12];
        int e0 = (t & 3) * 4;
        float2* exy = &sxy[quad * 16];
        float*  ez  = &szl[quad * 16];
#pragma unroll
        for (int e = 0; e < 4; ++e) {
            int i = e0 + e;
            float sx = 0.f, sy = 0.f, sz = 0.f;
            if (i & 1) { sx += v0.x; sy += v0.y; sz += v0.z; }
            if (i & 2) { sx += v1.x; sy += v1.y; sz += v1.z; }
            if (i & 4) { sx += v2.x; sy += v2.y; sz += v2.z; }
            if (i & 8) { sx += v3.x; sy += v3.y; sz += v3.z; }
            exy[i] = make_float2(sx, sy);
            ez[i]  = sz;
        }
    }
    __syncthreads();

    int row = b * NN + rt * 256 + t;

    const uint4* gw = (const uint4*)(g_bits + (size_t)row * WROW + s * 8);
    uint4 w0 = gw[0], w1 = gw[1];
    unsigned words[8] = { w0.x, w0.y, w0.z, w0.w, w1.x, w1.y, w1.z, w1.w };

    unsigned bxy = (unsigned)__cvta_generic_to_shared(sxy);
    unsigned bz  = (unsigned)__cvta_generic_to_shared(szl);

    ull  accxy0 = 0ull, accxy1 = 0ull;
    float accz0 = 0.f,  accz1 = 0.f;

#pragma unroll
    for (int wl = 0; wl < 8; ++wl) {
        unsigned w = words[wl];
        unsigned rxy = bxy + wl * 1024;   // 8 quads * 128B
        unsigned rz  = bz  + wl * 512;    // 8 quads * 64B
#pragma unroll
        for (int k = 0; k < 8; k += 2) {
            unsigned idx0 = (w >> (4 * k)) & 15u;
            unsigned idx1 = (w >> (4 * k + 4)) & 15u;
            unsigned axy0 = rxy + k * 128 + idx0 * 8;
            unsigned axy1 = rxy + k * 128 + 128 + idx1 * 8;
            unsigned az0  = rz  + k * 64 + idx0 * 4;
            unsigned az1  = rz  + k * 64 + 64 + idx1 * 4;
            ull vxy0, vxy1;
            float vz0, vz1;
            asm volatile("ld.shared.b64 %0, [%1];" : "=l"(vxy0) : "r"(axy0));
            asm volatile("ld.shared.b64 %0, [%1];" : "=l"(vxy1) : "r"(axy1));
            asm volatile("ld.shared.f32 %0, [%1];" : "=f"(vz0) : "r"(az0));
            asm volatile("ld.shared.f32 %0, [%1];" : "=f"(vz1) : "r"(az1));
            asm volatile("add.rn.f32x2 %0, %0, %1;" : "+l"(accxy0) : "l"(vxy0));
            asm volatile("add.rn.f32x2 %0, %0, %1;" : "+l"(accxy1) : "l"(vxy1));
            accz0 += vz0;
            accz1 += vz1;
        }
    }

    ull accxy;
    asm volatile("add.rn.f32x2 %0, %1, %2;" : "=l"(accxy) : "l"(accxy0), "l"(accxy1));
    float ax, ay;
    asm volatile("mov.b64 {%0, %1}, %2;" : "=f"(ax), "=f"(ay) : "l"(accxy));
    part[s * ROWS + row] = make_float4(ax, ay, accz0 + accz1, 0.f);
}

// ---------------- agg layer 1 + fused v2 epilogue (last-arriving block) --------
__global__ void __launch_bounds__(256) agg1_kernel(
    const float* __restrict__ W2, const float* __restrict__ b1)
{
    int bx = blockIdx.x;
    int b  = bx >> 8;
    int rt = (bx >> 4) & 15;
    int s  = bx & 15;
    int t  = threadIdx.x;

    agg_core(g_v, g_pa, b, rt, s, t);

    __shared__ unsigned s_last;
    __threadfence();
    __syncthreads();
    if (t == 0) s_last = atomicAdd(&g_ctr0[b * 16 + rt], 1u);
    __syncthreads();
    if (s_last == 15u) {
        __threadfence();
        int id = b * NN + rt * 256 + t;
        float sx = 0.f, sy = 0.f, sz = 0.f;
#pragma unroll
        for (int qq = 0; qq < NQ; ++qq) {
            float4 p = __ldcg(&g_pa[qq * ROWS + id]);
            sx += p.x; sy += p.y; sz += p.z;
        }
        float d = g_dinv[id];
        float h0 = fmaxf(d * sx + b1[0], 0.f);
        float h1 = fmaxf(d * sy + b1[1], 0.f);
        float h2 = fmaxf(d * sz + b1[2], 0.f);
        float u0 = h0*W2[0] + h1*W2[3] + h2*W2[6];
        float u1 = h0*W2[1] + h1*W2[4] + h2*W2[7];
        float u2 = h0*W2[2] + h1*W2[5] + h2*W2[8];
        g_v2[id] = make_float4(d*u0, d*u1, d*u2, 0.f);
    }
}

// ---------------- agg layer 2 + fused combine2 epilogue ----------------
__global__ void __launch_bounds__(256) agg2_kernel(const float* __restrict__ b2)
{
    int bx = blockIdx.x;
    int b  = bx >> 8;
    int rt = (bx >> 4) & 15;
    int s  = bx & 15;
    int t  = threadIdx.x;

    agg_core(g_v2, g_pb, b, rt, s, t);

    __shared__ unsigned s_last;
    __threadfence();
    __syncthreads();
    if (t == 0) s_last = atomicAdd(&g_ctr1[b * 16 + rt], 1u);
    __syncthreads();
    if (s_last == 15u) {
        __threadfence();
        int id = b * NN + rt * 256 + t;
        float sx = 0.f, sy = 0.f, sz = 0.f;
#pragma unroll
        for (int qq = 0; qq < NQ; ++qq) {
            float4 p = __ldcg(&g_pb[qq * ROWS + id]);
            sx += p.x; sy += p.y; sz += p.z;
        }
        float d = g_dinv[id];
        g_h2[id] = make_float4(d * sx + b2[0], d * sy + b2[1], d * sz + b2[2], 0.f);
    }
}

// ---------------- fc1: one chunk serves ALL 8 batches ---------------------------
// Block = 4 warps, chunk s covers rows [s*CK, s*CK+CK). Warp w walks rows with
// stride 4; lane owns cols 4l..4l+3 (one coalesced 512B fcW1 row load), applied
// to 8 batches via broadcast smem z. fcW1 is streamed from DRAM exactly once
// grid-wide (8x less traffic than per-batch chunks).
__global__ void __launch_bounds__(128) fc1_kernel(
    const float* __restrict__ idxin, const float* __restrict__ y,
    const float* __restrict__ fcW1, const float* __restrict__ fcW2,
    const float* __restrict__ fcb2, float* __restrict__ out)
{
    __shared__ float  zc[BB][CK + 1];
    __shared__ float4 sred[4][BB][32];   // 16 KB, 16B-aligned
    int s  = blockIdx.x;
    int k0 = s * CK;
    int klen = INDIM - k0;
    if (klen > CK) klen = CK;
    if (klen < 0) klen = 0;
    int t = threadIdx.x;
    int warp = t >> 5, lane = t & 31;

    // stage z for all 8 batches
    for (int idx = t; idx < BB * CK; idx += 128) {
        int b  = idx / CK;
        int kk = idx - b * CK;
        float z = 0.f;
        if (kk < klen) {
            int k = k0 + kk;
            if (k < NN) {
                z = idxin[b * NN + k];
            } else if (k < 4 * NN) {
                int g = k - NN;
                int i = g / 3;
                int f = g - i * 3;
                z = ((const float*)&g_h2[b * NN + i])[f];
            } else {
                z = y[b * 36 + (k - 4 * NN)];
            }
        }
        zc[b][kk] = z;
    }
    __syncthreads();

    const float4* W4 = (const float4*)fcW1;   // row k = W4[k*32 + lane]
    float4 acc[BB];
#pragma unroll
    for (int b = 0; b < BB; ++b) acc[b] = make_float4(0.f, 0.f, 0.f, 0.f);

#pragma unroll 2
    for (int kk = warp; kk < klen; kk += 4) {
        float4 w = W4[(size_t)(k0 + kk) * 32 + lane];
#pragma unroll
        for (int b = 0; b < BB; ++b) {
            float z = zc[b][kk];
            acc[b].x += z * w.x; acc[b].y += z * w.y;
            acc[b].z += z * w.z; acc[b].w += z * w.w;
        }
    }

    // cross-warp reduce, then 8 atomics per thread (spread addresses)
#pragma unroll
    for (int b = 0; b < BB; ++b)
        sred[warp][b][lane] = acc[b];
    __syncthreads();
#pragma unroll
    for (int b = 0; b < BB; ++b) {
        float v = ((const float*)sred[0][b])[t] + ((const float*)sred[1][b])[t]
                + ((const float*)sred[2][b])[t] + ((const float*)sred[3][b])[t];
        atomicAdd(&g_zacc[b * HID + t], v);
    }

    // last of the FCSPLIT blocks computes fc2 (128 = 8 batches x 16 actions)
    __shared__ unsigned s_last;
    __threadfence();
    __syncthreads();
    if (t == 0) s_last = atomicAdd(&g_fcc, 1u);
    __syncthreads();
    if (s_last == (unsigned)(FCSPLIT - 1)) {
        __threadfence();
        int ob = t >> 4;          // batch
        int oa = t & 15;          // action
        float o = fcb2[oa];
#pragma unroll 8
        for (int h = 0; h < HID; ++h)
            o += fmaxf(__ldcg(&g_zacc[ob * HID + h]), 0.f) * fcW2[h * NACT + oa];
        out[ob * NACT + oa] = o;
    }
}

// ---------------- launch ----------------
extern "C" void kernel_launch(void* const* d_in, const int* in_sizes, int n_in,
                              void* d_out, int out_size)
{
    const float* idxin = (const float*)d_in[0];   // [8,4096]
    const float* x     = (const float*)d_in[1];   // [8,4096,3]
    const float* y     = (const float*)d_in[2];   // [8,12,3]
    const int*   adj   = (const int*)  d_in[3];   // [8,4096,4096]
    const float* W1    = (const float*)d_in[4];
    const float* b1    = (const float*)d_in[5];
    const float* W2    = (const float*)d_in[6];
    const float* b2    = (const float*)d_in[7];
    const float* fcW1  = (const float*)d_in[8];
    const float* fcb1  = (const float*)d_in[9];
    const float* fcW2  = (const float*)d_in[10];
    const float* fcb2  = (const float*)d_in[11];
    float* out = (float*)d_out;

    prep_kernel<<<ROWS / 8, 256>>>(adj, x, W1, fcb1);
    agg1_kernel<<<2048, 256>>>(W2, b1);
    agg2_kernel<<<2048, 256>>>(b2);
    fc1_kernel<<<FCSPLIT, 128>>>(idxin, y, fcW1, fcW2, fcb2, out);
}